// round 1
// baseline (speedup 1.0000x reference)
#include <cuda_runtime.h>
#include <cuda_bf16.h>
#include <cstdint>
#include <cstdio>

// ---------------------------------------------------------------------------
// Problem constants
// ---------------------------------------------------------------------------
#define BB   4
#define TTT  4096
#define CC   1024
#define HH   16
#define HS   64          // head size K = C/H
#define TCH  128         // chunk length T
#define NCH  (TTT / TCH) // 32 chunks
#define MM   (BB * TTT)  // 16384 rows

// ---------------------------------------------------------------------------
// Device scratch (no cudaMalloc allowed)
// ---------------------------------------------------------------------------
__device__ float g_xr[(size_t)MM * CC];
__device__ float g_xk[(size_t)MM * CC];
__device__ float g_xv[(size_t)MM * CC];
__device__ float g_xg[(size_t)MM * CC];
__device__ float g_r [(size_t)MM * CC];
__device__ float g_k [(size_t)MM * CC];
__device__ float g_v [(size_t)MM * CC];
__device__ float g_g [(size_t)MM * CC];
__device__ float g_xo[(size_t)MM * CC];
__device__ float g_yg[(size_t)MM * CC];

// ---------------------------------------------------------------------------
// 1) time-shift + 4-way mix (float4)
// ---------------------------------------------------------------------------
__global__ __launch_bounds__(256) void mix_kernel(
    const float* __restrict__ x,
    const float* __restrict__ tmk, const float* __restrict__ tmv,
    const float* __restrict__ tmr, const float* __restrict__ tmg,
    float* __restrict__ xr, float* __restrict__ xk,
    float* __restrict__ xv, float* __restrict__ xg)
{
    int idx = blockIdx.x * blockDim.x + threadIdx.x;   // float4 index
    const int C4 = CC / 4;
    if (idx >= MM * C4) return;
    int c4 = idx % C4;
    int t  = (idx / C4) % TTT;

    float4 xc = ((const float4*)x)[idx];
    float4 xp = (t > 0) ? ((const float4*)x)[idx - C4] : make_float4(0.f, 0.f, 0.f, 0.f);

    float4 mk = ((const float4*)tmk)[c4];
    float4 mv = ((const float4*)tmv)[c4];
    float4 mr = ((const float4*)tmr)[c4];
    float4 mg = ((const float4*)tmg)[c4];

#define MIXV(out, m)                                                     \
    {                                                                    \
        float4 o;                                                        \
        o.x = xp.x + m.x * (xc.x - xp.x);                                \
        o.y = xp.y + m.y * (xc.y - xp.y);                                \
        o.z = xp.z + m.z * (xc.z - xp.z);                                \
        o.w = xp.w + m.w * (xc.w - xp.w);                                \
        ((float4*)out)[idx] = o;                                         \
    }
    MIXV(xr, mr); MIXV(xk, mk); MIXV(xv, mv); MIXV(xg, mg);
#undef MIXV
}

// ---------------------------------------------------------------------------
// 2) SGEMM: Cout[m,n] = sum_k A[m,k] * W[n,k]   (A: MxK row-major, W: NxK row-major)
//    128x128 block tile, BK=8, 8x8 per thread (split 4x4 quadrants).
//    epi: 0 = none, 1 = silu
// ---------------------------------------------------------------------------
__global__ __launch_bounds__(256) void sgemm_xwT(
    const float* __restrict__ A, const float* __restrict__ W,
    float* __restrict__ Cout, int M, int N, int Kd, int epi)
{
    __shared__ float As[8][128];
    __shared__ float Bs[8][128];

    const int tid = threadIdx.x;
    const int tx = tid & 15;        // 0..15 (cols)
    const int ty = tid >> 4;        // 0..15 (rows)
    const int m0 = blockIdx.y * 128;
    const int n0 = blockIdx.x * 128;

    const int lrow = tid >> 1;          // 0..127
    const int lk4  = (tid & 1) * 4;     // 0 or 4
    const float* Ag = A + (size_t)(m0 + lrow) * Kd + lk4;
    const float* Wg = W + (size_t)(n0 + lrow) * Kd + lk4;

    float acc[8][8];
#pragma unroll
    for (int i = 0; i < 8; i++)
#pragma unroll
        for (int j = 0; j < 8; j++) acc[i][j] = 0.f;

    for (int k0 = 0; k0 < Kd; k0 += 8) {
        float4 a4 = *(const float4*)(Ag + k0);
        float4 w4 = *(const float4*)(Wg + k0);
        __syncthreads();
        As[lk4 + 0][lrow] = a4.x; As[lk4 + 1][lrow] = a4.y;
        As[lk4 + 2][lrow] = a4.z; As[lk4 + 3][lrow] = a4.w;
        Bs[lk4 + 0][lrow] = w4.x; Bs[lk4 + 1][lrow] = w4.y;
        Bs[lk4 + 2][lrow] = w4.z; Bs[lk4 + 3][lrow] = w4.w;
        __syncthreads();

#pragma unroll
        for (int kk = 0; kk < 8; kk++) {
            float ra[8], rb[8];
            float4 t0 = *(const float4*)&As[kk][ty * 4];
            float4 t1 = *(const float4*)&As[kk][64 + ty * 4];
            ra[0] = t0.x; ra[1] = t0.y; ra[2] = t0.z; ra[3] = t0.w;
            ra[4] = t1.x; ra[5] = t1.y; ra[6] = t1.z; ra[7] = t1.w;
            float4 s0 = *(const float4*)&Bs[kk][tx * 4];
            float4 s1 = *(const float4*)&Bs[kk][64 + tx * 4];
            rb[0] = s0.x; rb[1] = s0.y; rb[2] = s0.z; rb[3] = s0.w;
            rb[4] = s1.x; rb[5] = s1.y; rb[6] = s1.z; rb[7] = s1.w;
#pragma unroll
            for (int i = 0; i < 8; i++)
#pragma unroll
                for (int j = 0; j < 8; j++)
                    acc[i][j] = fmaf(ra[i], rb[j], acc[i][j]);
        }
    }

#pragma unroll
    for (int i = 0; i < 8; i++) {
        int m = m0 + ((i < 4) ? (ty * 4 + i) : (64 + ty * 4 + (i - 4)));
#pragma unroll
        for (int j = 0; j < 8; j++) {
            int ncol = n0 + ((j < 4) ? (tx * 4 + j) : (64 + tx * 4 + (j - 4)));
            float val = acc[i][j];
            if (epi == 1) val = val / (1.f + expf(-val));   // silu
            Cout[(size_t)m * N + ncol] = val;
        }
    }
}

// ---------------------------------------------------------------------------
// 3) Chunked WKV. One block per (b,h). State (64x64) persistent in smem.
// ---------------------------------------------------------------------------
#define WKV_SMEM_FLOATS (132 + 3 * 128 * 65 + 128 * 129 + 64 * 65)
#define WKV_SMEM_BYTES  (WKV_SMEM_FLOATS * 4)

__global__ __launch_bounds__(256) void wkv_kernel(
    const float* __restrict__ R, const float* __restrict__ Km,
    const float* __restrict__ V, float* __restrict__ XO,
    const float* __restrict__ tdecay, const float* __restrict__ tfaaaa)
{
    extern __shared__ float sm[];
    float* pw   = sm;                  // decay^i, i=0..128
    float* r_s  = sm + 132;            // [128][65]
    float* k_s  = r_s + 128 * 65;
    float* v_s  = k_s + 128 * 65;
    float* attS = v_s + 128 * 65;      // [128][129]
    float* s_st = attS + 128 * 129;    // [64][65]

    const int tid = threadIdx.x;
    const int b = blockIdx.x >> 4;
    const int h = blockIdx.x & 15;
    const float decay = __expf(-__expf(tdecay[h]));
    const float u = tfaaaa[h];

    for (int i = tid; i < 132; i += 256) pw[i] = (i <= 128) ? powf(decay, (float)i) : 0.f;
    for (int i = tid; i < 64 * 65; i += 256) s_st[i] = 0.f;
    __syncthreads();
    const float ws = pw[128];

    const int tx = tid & 15, ty = tid >> 4;
    const size_t bbase = (size_t)b * TTT * CC + (size_t)h * HS;

    for (int n = 0; n < NCH; n++) {
        const size_t cbase = bbase + (size_t)n * TCH * CC;

        // ---- load chunk r,k,v (128 x 64), padded rows (stride 65)
        for (int e = tid; e < 128 * 16; e += 256) {
            int i = e >> 4, c4 = (e & 15) * 4;
            size_t gofs = cbase + (size_t)i * CC + c4;
            float4 rv = *(const float4*)(R + gofs);
            float4 kv = *(const float4*)(Km + gofs);
            float4 vv = *(const float4*)(V + gofs);
            float* rd = r_s + i * 65 + c4;
            rd[0] = rv.x; rd[1] = rv.y; rd[2] = rv.z; rd[3] = rv.w;
            float* kd = k_s + i * 65 + c4;
            kd[0] = kv.x; kd[1] = kv.y; kd[2] = kv.z; kd[3] = kv.w;
            float* vd = v_s + i * 65 + c4;
            vd[0] = vv.x; vd[1] = vv.y; vd[2] = vv.z; vd[3] = vv.w;
        }
        __syncthreads();

        // ---- att[i][j] = (r_i . k_j) * wmat(i,j)
        {
            float acc[8][8];
#pragma unroll
            for (int i = 0; i < 8; i++)
#pragma unroll
                for (int j = 0; j < 8; j++) acc[i][j] = 0.f;

            for (int kk = 0; kk < 64; kk++) {
                float ra[8], rb[8];
#pragma unroll
                for (int q = 0; q < 4; q++) {
                    ra[q]     = r_s[(ty * 4 + q) * 65 + kk];
                    ra[4 + q] = r_s[(64 + ty * 4 + q) * 65 + kk];
                    rb[q]     = k_s[(tx * 4 + q) * 65 + kk];
                    rb[4 + q] = k_s[(64 + tx * 4 + q) * 65 + kk];
                }
#pragma unroll
                for (int i = 0; i < 8; i++)
#pragma unroll
                    for (int j = 0; j < 8; j++)
                        acc[i][j] = fmaf(ra[i], rb[j], acc[i][j]);
            }
#pragma unroll
            for (int i = 0; i < 8; i++) {
                int ri = (i < 4) ? (ty * 4 + i) : (64 + ty * 4 + (i - 4));
#pragma unroll
                for (int j = 0; j < 8; j++) {
                    int cj = (j < 4) ? (tx * 4 + j) : (64 + tx * 4 + (j - 4));
                    int d = ri - cj;
                    float w = (d > 0) ? pw[d - 1] : ((d == 0) ? u : 0.f);
                    attS[ri * 129 + cj] = acc[i][j] * w;
                }
            }
        }
        __syncthreads();

        // ---- out[i][c] = sum_j att[i][j]*v[j][c] + pw[i]*sum_k r[i][k]*s[k][c]
        {
            float acc2[8][4], acc3[8][4];
#pragma unroll
            for (int i = 0; i < 8; i++)
#pragma unroll
                for (int j = 0; j < 4; j++) { acc2[i][j] = 0.f; acc3[i][j] = 0.f; }

            for (int j = 0; j < 128; j++) {
                float a[8], vv4[4];
#pragma unroll
                for (int q = 0; q < 4; q++) {
                    a[q]     = attS[(ty * 4 + q) * 129 + j];
                    a[4 + q] = attS[(64 + ty * 4 + q) * 129 + j];
                    vv4[q]   = v_s[j * 65 + tx * 4 + q];
                }
#pragma unroll
                for (int i = 0; i < 8; i++)
#pragma unroll
                    for (int c = 0; c < 4; c++)
                        acc2[i][c] = fmaf(a[i], vv4[c], acc2[i][c]);
            }
            for (int kk = 0; kk < 64; kk++) {
                float a[8], sv[4];
#pragma unroll
                for (int q = 0; q < 4; q++) {
                    a[q]     = r_s[(ty * 4 + q) * 65 + kk];
                    a[4 + q] = r_s[(64 + ty * 4 + q) * 65 + kk];
                    sv[q]    = s_st[kk * 65 + tx * 4 + q];
                }
#pragma unroll
                for (int i = 0; i < 8; i++)
#pragma unroll
                    for (int c = 0; c < 4; c++)
                        acc3[i][c] = fmaf(a[i], sv[c], acc3[i][c]);
            }
#pragma unroll
            for (int i = 0; i < 8; i++) {
                int ri = (i < 4) ? (ty * 4 + i) : (64 + ty * 4 + (i - 4));
                float wbv = pw[ri];
#pragma unroll
                for (int c = 0; c < 4; c++)
                    XO[cbase + (size_t)ri * CC + tx * 4 + c] =
                        acc2[i][c] + wbv * acc3[i][c];
            }
        }
        __syncthreads();

        // ---- state: s[k][c] = ws*s[k][c] + sum_j k[j][k]*pw[127-j]*v[j][c]
        {
            float acc4[4][4];
#pragma unroll
            for (int i = 0; i < 4; i++)
#pragma unroll
                for (int j = 0; j < 4; j++) acc4[i][j] = 0.f;

            for (int j = 0; j < 128; j++) {
                float wkj = pw[127 - j];
                float kw[4], vv4[4];
#pragma unroll
                for (int q = 0; q < 4; q++) {
                    kw[q]  = k_s[j * 65 + ty * 4 + q] * wkj;
                    vv4[q] = v_s[j * 65 + tx * 4 + q];
                }
#pragma unroll
                for (int i = 0; i < 4; i++)
#pragma unroll
                    for (int c = 0; c < 4; c++)
                        acc4[i][c] = fmaf(kw[i], vv4[c], acc4[i][c]);
            }
#pragma unroll
            for (int i = 0; i < 4; i++)
#pragma unroll
                for (int c = 0; c < 4; c++) {
                    int idx = (ty * 4 + i) * 65 + tx * 4 + c;
                    s_st[idx] = ws * s_st[idx] + acc4[i][c];
                }
        }
        __syncthreads();
    }
}

// ---------------------------------------------------------------------------
// 4) GroupNorm(H groups) over /8 scaled xo, then gate with g -> yg
//    one warp per (row, head): lanes cover channels lane and lane+32
// ---------------------------------------------------------------------------
__global__ __launch_bounds__(256) void gn_gate_kernel(
    const float* __restrict__ xo, const float* __restrict__ gg,
    const float* __restrict__ lnw, const float* __restrict__ lnb,
    float* __restrict__ yg)
{
    int warp = threadIdx.x >> 5, lane = threadIdx.x & 31;
    int gw = blockIdx.x * 8 + warp;   // over MM*HH
    int h = gw % HH;
    int row = gw / HH;
    size_t base = (size_t)row * CC + h * HS;

    float a = xo[base + lane] * 0.125f;
    float b = xo[base + 32 + lane] * 0.125f;
    float s = a + b, ss = a * a + b * b;
#pragma unroll
    for (int o = 16; o > 0; o >>= 1) {
        s  += __shfl_xor_sync(0xffffffffu, s,  o);
        ss += __shfl_xor_sync(0xffffffffu, ss, o);
    }
    float mean = s * (1.f / 64.f);
    float var  = ss * (1.f / 64.f) - mean * mean;
    float inv  = rsqrtf(var + 1e-5f);

    int c0 = h * HS + lane, c1 = c0 + 32;
    float y0 = (a - mean) * inv * lnw[c0] + lnb[c0];
    float y1 = (b - mean) * inv * lnw[c1] + lnb[c1];
    yg[base + lane]      = y0 * gg[base + lane];
    yg[base + 32 + lane] = y1 * gg[base + 32 + lane];
}

// ---------------------------------------------------------------------------
// Launch
// ---------------------------------------------------------------------------
extern "C" void kernel_launch(void* const* d_in, const int* in_sizes, int n_in,
                              void* d_out, int out_size)
{
    const float* x      = (const float*)d_in[0];
    const float* tmk    = (const float*)d_in[1];
    const float* tmv    = (const float*)d_in[2];
    const float* tmr    = (const float*)d_in[3];
    const float* tmg    = (const float*)d_in[4];
    const float* tdecay = (const float*)d_in[5];
    const float* tfaaaa = (const float*)d_in[6];
    const float* Wr     = (const float*)d_in[7];
    const float* Wk     = (const float*)d_in[8];
    const float* Wv     = (const float*)d_in[9];
    const float* Wg     = (const float*)d_in[10];
    const float* Wo     = (const float*)d_in[11];
    const float* lnw    = (const float*)d_in[12];
    const float* lnb    = (const float*)d_in[13];
    float* out = (float*)d_out;

    float *xr, *xk, *xv, *xg, *r, *k, *v, *g, *xo, *yg;
    cudaGetSymbolAddress((void**)&xr, g_xr);
    cudaGetSymbolAddress((void**)&xk, g_xk);
    cudaGetSymbolAddress((void**)&xv, g_xv);
    cudaGetSymbolAddress((void**)&xg, g_xg);
    cudaGetSymbolAddress((void**)&r,  g_r);
    cudaGetSymbolAddress((void**)&k,  g_k);
    cudaGetSymbolAddress((void**)&v,  g_v);
    cudaGetSymbolAddress((void**)&g,  g_g);
    cudaGetSymbolAddress((void**)&xo, g_xo);
    cudaGetSymbolAddress((void**)&yg, g_yg);

    cudaFuncSetAttribute(wkv_kernel,
                         cudaFuncAttributeMaxDynamicSharedMemorySize,
                         WKV_SMEM_BYTES);

    // 1) mix
    {
        int total4 = MM * CC / 4;
        mix_kernel<<<(total4 + 255) / 256, 256>>>(x, tmk, tmv, tmr, tmg,
                                                  xr, xk, xv, xg);
    }

    // 2) projections
    dim3 ggrid(CC / 128, MM / 128);   // (8, 128)
    sgemm_xwT<<<ggrid, 256>>>(xr, Wr, r, MM, CC, CC, 0);
    sgemm_xwT<<<ggrid, 256>>>(xk, Wk, k, MM, CC, CC, 0);
    sgemm_xwT<<<ggrid, 256>>>(xv, Wv, v, MM, CC, CC, 0);
    sgemm_xwT<<<ggrid, 256>>>(xg, Wg, g, MM, CC, CC, 1);   // silu

    // 3) WKV
    wkv_kernel<<<BB * HH, 256, WKV_SMEM_BYTES>>>(r, k, v, xo, tdecay, tfaaaa);

    // 4) GroupNorm + gate
    gn_gate_kernel<<<MM * HH / 8, 256>>>(xo, g, lnw, lnb, yg);

    // 5) output projection
    sgemm_xwT<<<ggrid, 256>>>(yg, Wo, out, MM, CC, CC, 0);
}

// round 3
// speedup vs baseline: 1.9209x; 1.9209x over previous
#include <cuda_runtime.h>
#include <cuda_bf16.h>
#include <cstdint>

// ---------------------------------------------------------------------------
// Problem constants
// ---------------------------------------------------------------------------
#define BB   4
#define TTT  4096
#define CC   1024
#define HH   16
#define HS   64
#define TCH  128
#define NCH  (TTT / TCH)
#define MM   (BB * TTT)      // 16384 rows
#define KD2  2048            // [hi(1024) | lo(1024)] concat width

// ---------------------------------------------------------------------------
// Device scratch (no cudaMalloc allowed)
// ---------------------------------------------------------------------------
__device__ __nv_bfloat16 g_xr[(size_t)MM * KD2];
__device__ __nv_bfloat16 g_xk[(size_t)MM * KD2];
__device__ __nv_bfloat16 g_xv[(size_t)MM * KD2];
__device__ __nv_bfloat16 g_xg[(size_t)MM * KD2];
__device__ __nv_bfloat16 g_ygb[(size_t)MM * KD2];
__device__ __nv_bfloat16 g_Wr[(size_t)CC * KD2];
__device__ __nv_bfloat16 g_Wk[(size_t)CC * KD2];
__device__ __nv_bfloat16 g_Wv[(size_t)CC * KD2];
__device__ __nv_bfloat16 g_Wg[(size_t)CC * KD2];
__device__ __nv_bfloat16 g_Wo[(size_t)CC * KD2];
__device__ float g_r [(size_t)MM * CC];
__device__ float g_k [(size_t)MM * CC];
__device__ float g_v [(size_t)MM * CC];
__device__ float g_g [(size_t)MM * CC];
__device__ float g_xo[(size_t)MM * CC];
__device__ float g_state[(size_t)BB * HH * NCH * HS * HS];  // 33.5 MB

// ---------------------------------------------------------------------------
// Helpers
// ---------------------------------------------------------------------------
__device__ __forceinline__ uint32_t smem_u32(const void* p) {
    uint32_t a;
    asm("{ .reg .u64 t; cvta.to.shared.u64 t, %1; cvt.u32.u64 %0, t; }"
        : "=r"(a) : "l"(p));
    return a;
}

__device__ __forceinline__ void cp_async16(uint32_t dst, const void* src) {
    asm volatile("cp.async.cg.shared.global [%0], [%1], 16;" :: "r"(dst), "l"(src));
}
#define CP_COMMIT() asm volatile("cp.async.commit_group;" ::: "memory")
#define CP_WAIT1()  asm volatile("cp.async.wait_group 1;" ::: "memory")
#define CP_WAIT0()  asm volatile("cp.async.wait_group 0;" ::: "memory")

__device__ __forceinline__ void ldm_x4(uint32_t& r0, uint32_t& r1,
                                       uint32_t& r2, uint32_t& r3, uint32_t addr) {
    asm volatile("ldmatrix.sync.aligned.m8n8.x4.shared.b16 {%0,%1,%2,%3}, [%4];"
                 : "=r"(r0), "=r"(r1), "=r"(r2), "=r"(r3) : "r"(addr));
}

__device__ __forceinline__ void mma_bf16(float& c0, float& c1, float& c2, float& c3,
                                         uint32_t a0, uint32_t a1, uint32_t a2, uint32_t a3,
                                         uint32_t b0, uint32_t b1) {
    asm volatile("mma.sync.aligned.m16n8k16.row.col.f32.bf16.bf16.f32 "
                 "{%0,%1,%2,%3}, {%4,%5,%6,%7}, {%8,%9}, {%0,%1,%2,%3};"
                 : "+f"(c0), "+f"(c1), "+f"(c2), "+f"(c3)
                 : "r"(a0), "r"(a1), "r"(a2), "r"(a3), "r"(b0), "r"(b1));
}

// smem tile: 128 rows x 32 bf16 (64B/row), 16B chunks XOR-swizzled
__device__ __forceinline__ uint32_t swz(int row, int chunk) {
    return (uint32_t)(row * 64 + ((chunk ^ ((row >> 1) & 3)) << 4));
}

__device__ __forceinline__ void split_bf16(float v, __nv_bfloat16& h, __nv_bfloat16& l) {
    h = __float2bfloat16(v);
    l = __float2bfloat16(v - __bfloat162float(h));
}

// ---------------------------------------------------------------------------
// 0) Weight conversion: W (CC x CC fp32) -> [hi | lo] (CC x KD2 bf16)
// ---------------------------------------------------------------------------
__global__ __launch_bounds__(256) void convw_kernel(
    const float* __restrict__ W, __nv_bfloat16* __restrict__ o)
{
    int idx = blockIdx.x * 256 + threadIdx.x;
    if (idx >= CC * CC) return;
    int r = idx >> 10, c = idx & 1023;
    __nv_bfloat16 h, l;
    split_bf16(W[idx], h, l);
    o[(size_t)r * KD2 + c] = h;
    o[(size_t)r * KD2 + 1024 + c] = l;
}

// ---------------------------------------------------------------------------
// 1) time-shift + 4-way mix -> bf16 hi/lo outputs
// ---------------------------------------------------------------------------
__global__ __launch_bounds__(256) void mix_kernel(
    const float* __restrict__ x,
    const float* __restrict__ tmk, const float* __restrict__ tmv,
    const float* __restrict__ tmr, const float* __restrict__ tmg,
    __nv_bfloat16* __restrict__ xr, __nv_bfloat16* __restrict__ xk,
    __nv_bfloat16* __restrict__ xv, __nv_bfloat16* __restrict__ xg)
{
    int idx = blockIdx.x * blockDim.x + threadIdx.x;   // float4 index
    const int C4 = CC / 4;
    if (idx >= MM * C4) return;
    int c4 = idx % C4;
    int row = idx / C4;
    int t = row % TTT;

    float4 xc = ((const float4*)x)[idx];
    float4 xp = (t > 0) ? ((const float4*)x)[idx - C4] : make_float4(0.f, 0.f, 0.f, 0.f);

    float4 mk = ((const float4*)tmk)[c4];
    float4 mv = ((const float4*)tmv)[c4];
    float4 mr = ((const float4*)tmr)[c4];
    float4 mg = ((const float4*)tmg)[c4];

    size_t base = (size_t)row * KD2 + c4 * 4;

#define MIXV(out, m)                                                          \
    {                                                                         \
        float o0 = xp.x + m.x * (xc.x - xp.x);                                \
        float o1 = xp.y + m.y * (xc.y - xp.y);                                \
        float o2 = xp.z + m.z * (xc.z - xp.z);                                \
        float o3 = xp.w + m.w * (xc.w - xp.w);                                \
        union { __nv_bfloat16 b[4]; uint2 u; } hi, lo;                        \
        split_bf16(o0, hi.b[0], lo.b[0]);                                     \
        split_bf16(o1, hi.b[1], lo.b[1]);                                     \
        split_bf16(o2, hi.b[2], lo.b[2]);                                     \
        split_bf16(o3, hi.b[3], lo.b[3]);                                     \
        *(uint2*)(out + base) = hi.u;                                         \
        *(uint2*)(out + base + 1024) = lo.u;                                  \
    }
    MIXV(xr, mr); MIXV(xk, mk); MIXV(xv, mv); MIXV(xg, mg);
#undef MIXV
}

// ---------------------------------------------------------------------------
// 2) bf16 mma.sync GEMM: C[m,n] = sum_k A[m,k]*W[n,k]  (bf16x3 split, f32 acc)
//    CTA 128x128, BK=32, 8 warps (4M x 2N), warp tile 32x64.
//    96 stages = 3 passes (hi*hi, hi*lo, lo*hi) x 32 k-blocks.
// ---------------------------------------------------------------------------
__global__ __launch_bounds__(256, 2) void gemm_mma(
    const __nv_bfloat16* __restrict__ A, const __nv_bfloat16* __restrict__ W,
    float* __restrict__ C, int epi)
{
    __shared__ __align__(128) char gsm[2][16384];   // [stage][A 8KB | B 8KB]

    const int tid = threadIdx.x;
    const int wid = tid >> 5, lane = tid & 31;
    const int wm = wid & 3;          // 0..3 -> M
    const int wn = wid >> 2;         // 0..1 -> N
    const int m0 = blockIdx.y * 128;
    const int n0 = blockIdx.x * 128;

    const uint32_t sa0 = smem_u32(&gsm[0][0]);

    float acc[2][8][4];
#pragma unroll
    for (int mt = 0; mt < 2; mt++)
#pragma unroll
        for (int nt = 0; nt < 8; nt++)
#pragma unroll
            for (int q = 0; q < 4; q++) acc[mt][nt][q] = 0.f;

    // loader indices: 512 A-chunks + 512 B-chunks per stage, 4 per thread
    const int lrowA = tid >> 1;                 // 0..127 (2 chunks each)
    const int lcA0 = (tid & 1) * 2;             // chunks {0,1} or {2,3}

    auto load_stage = [&](int s, int buf) {
        int p = s >> 5, kb = s & 31;
        int aoff = (p == 2) ? 1024 : 0;
        int boff = (p == 1) ? 1024 : 0;
        uint32_t ab = sa0 + buf * 16384;
        uint32_t bb = ab + 8192;
        const __nv_bfloat16* Ar = A + (size_t)(m0 + lrowA) * KD2 + aoff + kb * 32;
        const __nv_bfloat16* Br = W + (size_t)(n0 + lrowA) * KD2 + boff + kb * 32;
#pragma unroll
        for (int c = 0; c < 2; c++) {
            cp_async16(ab + swz(lrowA, lcA0 + c), Ar + (lcA0 + c) * 8);
            cp_async16(bb + swz(lrowA, lcA0 + c), Br + (lcA0 + c) * 8);
        }
    };

    const int NST = 96;
    load_stage(0, 0); CP_COMMIT();
    load_stage(1, 1); CP_COMMIT();

    for (int s = 0; s < NST; s++) {
        if (s < NST - 1) { CP_WAIT1(); } else { CP_WAIT0(); }
        __syncthreads();

        uint32_t ab = sa0 + (s & 1) * 16384;
        uint32_t bb = ab + 8192;
#pragma unroll
        for (int kk = 0; kk < 2; kk++) {
            uint32_t a[2][4];
#pragma unroll
            for (int mt = 0; mt < 2; mt++) {
                int row = wm * 32 + mt * 16 + (lane & 15);
                int ch = kk * 2 + (lane >> 4);
                ldm_x4(a[mt][0], a[mt][1], a[mt][2], a[mt][3], ab + swz(row, ch));
            }
            uint32_t b[8][2];
#pragma unroll
            for (int nq = 0; nq < 4; nq++) {
                int row = wn * 64 + nq * 16 + ((lane >> 4) & 1) * 8 + (lane & 7);
                int ch = kk * 2 + ((lane >> 3) & 1);
                ldm_x4(b[nq * 2][0], b[nq * 2][1], b[nq * 2 + 1][0], b[nq * 2 + 1][1],
                       bb + swz(row, ch));
            }
#pragma unroll
            for (int mt = 0; mt < 2; mt++)
#pragma unroll
                for (int nt = 0; nt < 8; nt++)
                    mma_bf16(acc[mt][nt][0], acc[mt][nt][1], acc[mt][nt][2], acc[mt][nt][3],
                             a[mt][0], a[mt][1], a[mt][2], a[mt][3],
                             b[nt][0], b[nt][1]);
        }
        __syncthreads();
        if (s + 2 < NST) { load_stage(s + 2, s & 1); CP_COMMIT(); }
    }

    // epilogue: direct float2 stores
#pragma unroll
    for (int mt = 0; mt < 2; mt++) {
        int gr = m0 + wm * 32 + mt * 16 + (lane >> 2);
#pragma unroll
        for (int nt = 0; nt < 8; nt++) {
            int gc = n0 + wn * 64 + nt * 8 + (lane & 3) * 2;
            float v0 = acc[mt][nt][0], v1 = acc[mt][nt][1];
            float v2 = acc[mt][nt][2], v3 = acc[mt][nt][3];
            if (epi) {
                v0 = v0 / (1.f + expf(-v0));
                v1 = v1 / (1.f + expf(-v1));
                v2 = v2 / (1.f + expf(-v2));
                v3 = v3 / (1.f + expf(-v3));
            }
            *(float2*)&C[(size_t)gr * CC + gc]       = make_float2(v0, v1);
            *(float2*)&C[(size_t)(gr + 8) * CC + gc] = make_float2(v2, v3);
        }
    }
}

// ---------------------------------------------------------------------------
// 3a) WKV phase 1: per (b,h,chunk) contribution G = (k .* wk)^T v  (64x64)
// ---------------------------------------------------------------------------
#define P1_SMEM_BYTES ((132 + 2 * 128 * 65) * 4)

__global__ __launch_bounds__(256) void wkv_phase1(
    const float* __restrict__ Km, const float* __restrict__ V,
    float* __restrict__ G, const float* __restrict__ tdecay)
{
    extern __shared__ float sm1[];
    float* pw  = sm1;               // decay^i, 0..127
    float* k_s = sm1 + 132;         // [128][65]
    float* v_s = k_s + 128 * 65;

    const int tid = threadIdx.x;
    const int bhn = blockIdx.x;
    const int n = bhn & 31, bh = bhn >> 5;
    const int b = bh >> 4, h = bh & 15;
    const float decay = __expf(-__expf(tdecay[h]));

    for (int i = tid; i < 128; i += 256) pw[i] = powf(decay, (float)i);
    const size_t cbase = (size_t)b * TTT * CC + (size_t)h * HS + (size_t)n * TCH * CC;

    for (int e = tid; e < 128 * 16; e += 256) {
        int i = e >> 4, c4 = (e & 15) * 4;
        size_t gofs = cbase + (size_t)i * CC + c4;
        float4 kv = *(const float4*)(Km + gofs);
        float4 vv = *(const float4*)(V + gofs);
        float* kd = k_s + i * 65 + c4;
        kd[0] = kv.x; kd[1] = kv.y; kd[2] = kv.z; kd[3] = kv.w;
        float* vd = v_s + i * 65 + c4;
        vd[0] = vv.x; vd[1] = vv.y; vd[2] = vv.z; vd[3] = vv.w;
    }
    __syncthreads();

    const int tx = tid & 15, ty = tid >> 4;
    float acc[4][4];
#pragma unroll
    for (int i = 0; i < 4; i++)
#pragma unroll
        for (int j = 0; j < 4; j++) acc[i][j] = 0.f;

    for (int j = 0; j < 128; j++) {
        float wkj = pw[127 - j];
        float kw[4], vv4[4];
#pragma unroll
        for (int q = 0; q < 4; q++) {
            kw[q]  = k_s[j * 65 + ty * 4 + q] * wkj;
            vv4[q] = v_s[j * 65 + tx * 4 + q];
        }
#pragma unroll
        for (int i = 0; i < 4; i++)
#pragma unroll
            for (int c = 0; c < 4; c++)
                acc[i][c] = fmaf(kw[i], vv4[c], acc[i][c]);
    }
    float* Gd = G + (size_t)bhn * (HS * HS);
#pragma unroll
    for (int i = 0; i < 4; i++)
#pragma unroll
        for (int c = 0; c < 4; c++)
            Gd[(ty * 4 + i) * 64 + tx * 4 + c] = acc[i][c];
}

// ---------------------------------------------------------------------------
// 3b) WKV phase 2: in-place scan  buf[n] <- S_n ; S_{n+1} = ws*S_n + G_n
// ---------------------------------------------------------------------------
__global__ __launch_bounds__(256) void wkv_scan(
    float* __restrict__ G, const float* __restrict__ tdecay)
{
    const int tid = threadIdx.x;
    const int bh = blockIdx.x;
    const int h = bh & 15;
    const float decay = __expf(-__expf(tdecay[h]));
    const float ws = powf(decay, 128.f);

    float s[16];
#pragma unroll
    for (int t = 0; t < 16; t++) s[t] = 0.f;

    float* base = G + (size_t)bh * NCH * (HS * HS);
    for (int n = 0; n < NCH; n++) {
        float* p = base + (size_t)n * (HS * HS);
#pragma unroll
        for (int t = 0; t < 16; t++) {
            int idx = tid + t * 256;
            float g = p[idx];
            p[idx] = s[t];
            s[t] = ws * s[t] + g;
        }
    }
}

// ---------------------------------------------------------------------------
// 3c) WKV phase 3: per (b,h,chunk) output
// ---------------------------------------------------------------------------
#define P3_SMEM_BYTES ((132 + 3 * 128 * 65 + 128 * 129 + 64 * 65) * 4)

__global__ __launch_bounds__(256) void wkv_phase3(
    const float* __restrict__ R, const float* __restrict__ Km,
    const float* __restrict__ V, const float* __restrict__ S,
    float* __restrict__ XO,
    const float* __restrict__ tdecay, const float* __restrict__ tfaaaa)
{
    extern __shared__ float sm[];
    float* pw   = sm;
    float* r_s  = sm + 132;
    float* k_s  = r_s + 128 * 65;
    float* v_s  = k_s + 128 * 65;
    float* attS = v_s + 128 * 65;
    float* s_st = attS + 128 * 129;

    const int tid = threadIdx.x;
    const int bhn = blockIdx.x;
    const int n = bhn & 31, bh = bhn >> 5;
    const int b = bh >> 4, h = bh & 15;
    const float decay = __expf(-__expf(tdecay[h]));
    const float u = tfaaaa[h];

    for (int i = tid; i < 128; i += 256) pw[i] = powf(decay, (float)i);

    const float* Sd = S + (size_t)bhn * (HS * HS);
    for (int i = tid; i < 64 * 16; i += 256) {
        int r4 = i >> 4, c4 = (i & 15) * 4;
        float4 sv = *(const float4*)(Sd + r4 * 64 + c4);
        float* d = s_st + r4 * 65 + c4;
        d[0] = sv.x; d[1] = sv.y; d[2] = sv.z; d[3] = sv.w;
    }

    const size_t cbase = (size_t)b * TTT * CC + (size_t)h * HS + (size_t)n * TCH * CC;
    for (int e = tid; e < 128 * 16; e += 256) {
        int i = e >> 4, c4 = (e & 15) * 4;
        size_t gofs = cbase + (size_t)i * CC + c4;
        float4 rv = *(const float4*)(R + gofs);
        float4 kv = *(const float4*)(Km + gofs);
        float4 vv = *(const float4*)(V + gofs);
        float* rd = r_s + i * 65 + c4;
        rd[0] = rv.x; rd[1] = rv.y; rd[2] = rv.z; rd[3] = rv.w;
        float* kd = k_s + i * 65 + c4;
        kd[0] = kv.x; kd[1] = kv.y; kd[2] = kv.z; kd[3] = kv.w;
        float* vd = v_s + i * 65 + c4;
        vd[0] = vv.x; vd[1] = vv.y; vd[2] = vv.z; vd[3] = vv.w;
    }
    __syncthreads();

    const int tx = tid & 15, ty = tid >> 4;

    // att[i][j] = (r_i . k_j) * wmat(i,j)
    {
        float acc[8][8];
#pragma unroll
        for (int i = 0; i < 8; i++)
#pragma unroll
            for (int j = 0; j < 8; j++) acc[i][j] = 0.f;

        for (int kk = 0; kk < 64; kk++) {
            float ra[8], rb[8];
#pragma unroll
            for (int q = 0; q < 4; q++) {
                ra[q]     = r_s[(ty * 4 + q) * 65 + kk];
                ra[4 + q] = r_s[(64 + ty * 4 + q) * 65 + kk];
                rb[q]     = k_s[(tx * 4 + q) * 65 + kk];
                rb[4 + q] = k_s[(64 + tx * 4 + q) * 65 + kk];
            }
#pragma unroll
            for (int i = 0; i < 8; i++)
#pragma unroll
                for (int j = 0; j < 8; j++)
                    acc[i][j] = fmaf(ra[i], rb[j], acc[i][j]);
        }
#pragma unroll
        for (int i = 0; i < 8; i++) {
            int ri = (i < 4) ? (ty * 4 + i) : (64 + ty * 4 + (i - 4));
#pragma unroll
            for (int j = 0; j < 8; j++) {
                int cj = (j < 4) ? (tx * 4 + j) : (64 + tx * 4 + (j - 4));
                int d = ri - cj;
                float w = (d > 0) ? pw[d - 1] : ((d == 0) ? u : 0.f);
                attS[ri * 129 + cj] = acc[i][j] * w;
            }
        }
    }
    __syncthreads();

    // out[i][c] = sum_j att[i][j]*v[j][c] + pw[i]*sum_k r[i][k]*s[k][c]
    {
        float acc2[8][4], acc3[8][4];
#pragma unroll
        for (int i = 0; i < 8; i++)
#pragma unroll
            for (int j = 0; j < 4; j++) { acc2[i][j] = 0.f; acc3[i][j] = 0.f; }

        for (int j = 0; j < 128; j++) {
            float a[8], vv4[4];
#pragma unroll
            for (int q = 0; q < 4; q++) {
                a[q]     = attS[(ty * 4 + q) * 129 + j];
                a[4 + q] = attS[(64 + ty * 4 + q) * 129 + j];
                vv4[q]   = v_s[j * 65 + tx * 4 + q];
            }
#pragma unroll
            for (int i = 0; i < 8; i++)
#pragma unroll
                for (int c = 0; c < 4; c++)
                    acc2[i][c] = fmaf(a[i], vv4[c], acc2[i][c]);
        }
        for (int kk = 0; kk < 64; kk++) {
            float a[8], sv[4];
#pragma unroll
            for (int q = 0; q < 4; q++) {
                a[q]     = r_s[(ty * 4 + q) * 65 + kk];
                a[4 + q] = r_s[(64 + ty * 4 + q) * 65 + kk];
                sv[q]    = s_st[kk * 65 + tx * 4 + q];
            }
#pragma unroll
            for (int i = 0; i < 8; i++)
#pragma unroll
                for (int c = 0; c < 4; c++)
                    acc3[i][c] = fmaf(a[i], sv[c], acc3[i][c]);
        }
#pragma unroll
        for (int i = 0; i < 8; i++) {
            int ri = (i < 4) ? (ty * 4 + i) : (64 + ty * 4 + (i - 4));
            float wbv = pw[ri];
#pragma unroll
            for (int c = 0; c < 4; c++)
                XO[cbase + (size_t)ri * CC + tx * 4 + c] =
                    acc2[i][c] + wbv * acc3[i][c];
        }
    }
}

// ---------------------------------------------------------------------------
// 4) GroupNorm + gate -> bf16 hi/lo output for final GEMM
// ---------------------------------------------------------------------------
__global__ __launch_bounds__(256) void gn_gate_kernel(
    const float* __restrict__ xo, const float* __restrict__ gg,
    const float* __restrict__ lnw, const float* __restrict__ lnb,
    __nv_bfloat16* __restrict__ yg)
{
    int warp = threadIdx.x >> 5, lane = threadIdx.x & 31;
    int gw = blockIdx.x * 8 + warp;   // over MM*HH
    int h = gw % HH;
    int row = gw / HH;
    size_t base = (size_t)row * CC + h * HS;

    float a = xo[base + lane] * 0.125f;
    float b = xo[base + 32 + lane] * 0.125f;
    float s = a + b, ss = a * a + b * b;
#pragma unroll
    for (int o = 16; o > 0; o >>= 1) {
        s  += __shfl_xor_sync(0xffffffffu, s,  o);
        ss += __shfl_xor_sync(0xffffffffu, ss, o);
    }
    float mean = s * (1.f / 64.f);
    float var  = ss * (1.f / 64.f) - mean * mean;
    float inv  = rsqrtf(var + 1e-5f);

    int c0 = h * HS + lane, c1 = c0 + 32;
    float y0 = ((a - mean) * inv * lnw[c0] + lnb[c0]) * gg[base + lane];
    float y1 = ((b - mean) * inv * lnw[c1] + lnb[c1]) * gg[base + 32 + lane];

    size_t b2 = (size_t)row * KD2;
    __nv_bfloat16 h0, l0, h1, l1;
    split_bf16(y0, h0, l0);
    split_bf16(y1, h1, l1);
    yg[b2 + c0]         = h0;
    yg[b2 + c1]         = h1;
    yg[b2 + 1024 + c0]  = l0;
    yg[b2 + 1024 + c1]  = l1;
}

// ---------------------------------------------------------------------------
// Launch
// ---------------------------------------------------------------------------
extern "C" void kernel_launch(void* const* d_in, const int* in_sizes, int n_in,
                              void* d_out, int out_size)
{
    const float* x      = (const float*)d_in[0];
    const float* tmk    = (const float*)d_in[1];
    const float* tmv    = (const float*)d_in[2];
    const float* tmr    = (const float*)d_in[3];
    const float* tmg    = (const float*)d_in[4];
    const float* tdecay = (const float*)d_in[5];
    const float* tfaaaa = (const float*)d_in[6];
    const float* Wr     = (const float*)d_in[7];
    const float* Wk     = (const float*)d_in[8];
    const float* Wv     = (const float*)d_in[9];
    const float* Wg     = (const float*)d_in[10];
    const float* Wo     = (const float*)d_in[11];
    const float* lnw    = (const float*)d_in[12];
    const float* lnb    = (const float*)d_in[13];
    float* out = (float*)d_out;

    __nv_bfloat16 *xr, *xk, *xv, *xg, *ygb, *wr, *wk, *wv, *wg, *wo;
    float *r, *k, *v, *g, *xo, *st;
    cudaGetSymbolAddress((void**)&xr,  g_xr);
    cudaGetSymbolAddress((void**)&xk,  g_xk);
    cudaGetSymbolAddress((void**)&xv,  g_xv);
    cudaGetSymbolAddress((void**)&xg,  g_xg);
    cudaGetSymbolAddress((void**)&ygb, g_ygb);
    cudaGetSymbolAddress((void**)&wr,  g_Wr);
    cudaGetSymbolAddress((void**)&wk,  g_Wk);
    cudaGetSymbolAddress((void**)&wv,  g_Wv);
    cudaGetSymbolAddress((void**)&wg,  g_Wg);
    cudaGetSymbolAddress((void**)&wo,  g_Wo);
    cudaGetSymbolAddress((void**)&r,   g_r);
    cudaGetSymbolAddress((void**)&k,   g_k);
    cudaGetSymbolAddress((void**)&v,   g_v);
    cudaGetSymbolAddress((void**)&g,   g_g);
    cudaGetSymbolAddress((void**)&xo,  g_xo);
    cudaGetSymbolAddress((void**)&st,  g_state);

    cudaFuncSetAttribute(wkv_phase1,
                         cudaFuncAttributeMaxDynamicSharedMemorySize, P1_SMEM_BYTES);
    cudaFuncSetAttribute(wkv_phase3,
                         cudaFuncAttributeMaxDynamicSharedMemorySize, P3_SMEM_BYTES);

    // 0) weight hi/lo conversion
    {
        int blocks = (CC * CC + 255) / 256;
        convw_kernel<<<blocks, 256>>>(Wr, wr);
        convw_kernel<<<blocks, 256>>>(Wk, wk);
        convw_kernel<<<blocks, 256>>>(Wv, wv);
        convw_kernel<<<blocks, 256>>>(Wg, wg);
        convw_kernel<<<blocks, 256>>>(Wo, wo);
    }

    // 1) mix -> bf16 hi/lo
    {
        int total4 = MM * CC / 4;
        mix_kernel<<<(total4 + 255) / 256, 256>>>(x, tmk, tmv, tmr, tmg,
                                                  xr, xk, xv, xg);
    }

    // 2) projections on tensor cores (mma.sync)
    dim3 ggrid(CC / 128, MM / 128);   // (8, 128)
    gemm_mma<<<ggrid, 256>>>(xr, wr, r, 0);
    gemm_mma<<<ggrid, 256>>>(xk, wk, k, 0);
    gemm_mma<<<ggrid, 256>>>(xv, wv, v, 0);
    gemm_mma<<<ggrid, 256>>>(xg, wg, g, 1);   // silu

    // 3) WKV: parallel contributions -> scan -> parallel outputs
    wkv_phase1<<<BB * HH * NCH, 256, P1_SMEM_BYTES>>>(k, v, st, tdecay);
    wkv_scan<<<BB * HH, 256>>>(st, tdecay);
    wkv_phase3<<<BB * HH * NCH, 256, P3_SMEM_BYTES>>>(r, k, v, st, xo,
                                                      tdecay, tfaaaa);

    // 4) GroupNorm + gate -> bf16 hi/lo
    gn_gate_kernel<<<MM * HH / 8, 256>>>(xo, g, lnw, lnb, ygb);

    // 5) output projection (writes d_out)
    gemm_mma<<<ggrid, 256>>>(ygb, wo, out, 0);
}

// round 4
// speedup vs baseline: 2.0921x; 1.0891x over previous
#include <cuda_runtime.h>
#include <cuda_bf16.h>
#include <cstdint>

// ---------------------------------------------------------------------------
// Problem constants
// ---------------------------------------------------------------------------
#define BB   4
#define TTT  4096
#define CC   1024
#define HH   16
#define HS   64
#define TCH  128
#define NCH  (TTT / TCH)
#define MM   (BB * TTT)      // 16384 rows
#define KD2  2048            // [hi(1024) | lo(1024)] concat width

// ---------------------------------------------------------------------------
// Device scratch (no cudaMalloc allowed)
// ---------------------------------------------------------------------------
__device__ __nv_bfloat16 g_xr[(size_t)MM * KD2];
__device__ __nv_bfloat16 g_xk[(size_t)MM * KD2];
__device__ __nv_bfloat16 g_xv[(size_t)MM * KD2];
__device__ __nv_bfloat16 g_xg[(size_t)MM * KD2];
__device__ __nv_bfloat16 g_ygb[(size_t)MM * KD2];
__device__ __nv_bfloat16 g_Wr[(size_t)CC * KD2];
__device__ __nv_bfloat16 g_Wk[(size_t)CC * KD2];
__device__ __nv_bfloat16 g_Wv[(size_t)CC * KD2];
__device__ __nv_bfloat16 g_Wg[(size_t)CC * KD2];
__device__ __nv_bfloat16 g_Wo[(size_t)CC * KD2];
__device__ float g_r [(size_t)MM * CC];
__device__ float g_k [(size_t)MM * CC];
__device__ float g_v [(size_t)MM * CC];
__device__ float g_g [(size_t)MM * CC];
__device__ float g_xo[(size_t)MM * CC];
__device__ float g_state[(size_t)BB * HH * NCH * HS * HS];  // 33.5 MB

// ---------------------------------------------------------------------------
// Helpers
// ---------------------------------------------------------------------------
__device__ __forceinline__ uint32_t smem_u32(const void* p) {
    uint32_t a;
    asm("{ .reg .u64 t; cvta.to.shared.u64 t, %1; cvt.u32.u64 %0, t; }"
        : "=r"(a) : "l"(p));
    return a;
}

__device__ __forceinline__ void cp_async16(uint32_t dst, const void* src) {
    asm volatile("cp.async.cg.shared.global [%0], [%1], 16;" :: "r"(dst), "l"(src));
}
#define CP_COMMIT() asm volatile("cp.async.commit_group;" ::: "memory")
#define CP_WAIT2()  asm volatile("cp.async.wait_group 2;" ::: "memory")

__device__ __forceinline__ void ldm_x4(uint32_t& r0, uint32_t& r1,
                                       uint32_t& r2, uint32_t& r3, uint32_t addr) {
    asm volatile("ldmatrix.sync.aligned.m8n8.x4.shared.b16 {%0,%1,%2,%3}, [%4];"
                 : "=r"(r0), "=r"(r1), "=r"(r2), "=r"(r3) : "r"(addr));
}

__device__ __forceinline__ void mma_bf16(float& c0, float& c1, float& c2, float& c3,
                                         uint32_t a0, uint32_t a1, uint32_t a2, uint32_t a3,
                                         uint32_t b0, uint32_t b1) {
    asm volatile("mma.sync.aligned.m16n8k16.row.col.f32.bf16.bf16.f32 "
                 "{%0,%1,%2,%3}, {%4,%5,%6,%7}, {%8,%9}, {%0,%1,%2,%3};"
                 : "+f"(c0), "+f"(c1), "+f"(c2), "+f"(c3)
                 : "r"(a0), "r"(a1), "r"(a2), "r"(a3), "r"(b0), "r"(b1));
}

// smem tile: 128 rows x 32 bf16 (64B/row), 16B chunks XOR-swizzled
__device__ __forceinline__ uint32_t swz(int row, int chunk) {
    return (uint32_t)(row * 64 + ((chunk ^ ((row >> 1) & 3)) << 4));
}

__device__ __forceinline__ void split_bf16(float v, __nv_bfloat16& h, __nv_bfloat16& l) {
    h = __float2bfloat16(v);
    l = __float2bfloat16(v - __bfloat162float(h));
}

// ---------------------------------------------------------------------------
// 0) Weight conversion (all 5 weights in one launch):
//    W (CC x CC fp32) -> [hi | lo] (CC x KD2 bf16)
// ---------------------------------------------------------------------------
__global__ __launch_bounds__(256) void convw_kernel(
    const float* __restrict__ W0, const float* __restrict__ W1,
    const float* __restrict__ W2, const float* __restrict__ W3,
    const float* __restrict__ W4,
    __nv_bfloat16* __restrict__ o0, __nv_bfloat16* __restrict__ o1,
    __nv_bfloat16* __restrict__ o2, __nv_bfloat16* __restrict__ o3,
    __nv_bfloat16* __restrict__ o4)
{
    const float* W;
    __nv_bfloat16* o;
    switch (blockIdx.y) {
        case 0: W = W0; o = o0; break;
        case 1: W = W1; o = o1; break;
        case 2: W = W2; o = o2; break;
        case 3: W = W3; o = o3; break;
        default: W = W4; o = o4; break;
    }
    int idx = blockIdx.x * 256 + threadIdx.x;
    if (idx >= CC * CC) return;
    int r = idx >> 10, c = idx & 1023;
    __nv_bfloat16 h, l;
    split_bf16(W[idx], h, l);
    o[(size_t)r * KD2 + c] = h;
    o[(size_t)r * KD2 + 1024 + c] = l;
}

// ---------------------------------------------------------------------------
// 1) time-shift + 4-way mix -> bf16 hi/lo outputs
// ---------------------------------------------------------------------------
__global__ __launch_bounds__(256) void mix_kernel(
    const float* __restrict__ x,
    const float* __restrict__ tmk, const float* __restrict__ tmv,
    const float* __restrict__ tmr, const float* __restrict__ tmg,
    __nv_bfloat16* __restrict__ xr, __nv_bfloat16* __restrict__ xk,
    __nv_bfloat16* __restrict__ xv, __nv_bfloat16* __restrict__ xg)
{
    int idx = blockIdx.x * blockDim.x + threadIdx.x;   // float4 index
    const int C4 = CC / 4;
    if (idx >= MM * C4) return;
    int c4 = idx % C4;
    int row = idx / C4;
    int t = row % TTT;

    float4 xc = ((const float4*)x)[idx];
    float4 xp = (t > 0) ? ((const float4*)x)[idx - C4] : make_float4(0.f, 0.f, 0.f, 0.f);

    float4 mk = ((const float4*)tmk)[c4];
    float4 mv = ((const float4*)tmv)[c4];
    float4 mr = ((const float4*)tmr)[c4];
    float4 mg = ((const float4*)tmg)[c4];

    size_t base = (size_t)row * KD2 + c4 * 4;

#define MIXV(out, m)                                                          \
    {                                                                         \
        float o0 = xp.x + m.x * (xc.x - xp.x);                                \
        float o1 = xp.y + m.y * (xc.y - xp.y);                                \
        float o2 = xp.z + m.z * (xc.z - xp.z);                                \
        float o3 = xp.w + m.w * (xc.w - xp.w);                                \
        union { __nv_bfloat16 b[4]; uint2 u; } hi, lo;                        \
        split_bf16(o0, hi.b[0], lo.b[0]);                                     \
        split_bf16(o1, hi.b[1], lo.b[1]);                                     \
        split_bf16(o2, hi.b[2], lo.b[2]);                                     \
        split_bf16(o3, hi.b[3], lo.b[3]);                                     \
        *(uint2*)(out + base) = hi.u;                                         \
        *(uint2*)(out + base + 1024) = lo.u;                                  \
    }
    MIXV(xr, mr); MIXV(xk, mk); MIXV(xv, mv); MIXV(xg, mg);
#undef MIXV
}

// ---------------------------------------------------------------------------
// 2) bf16 mma.sync GEMM: C[m,n] = sum_k A[m,k]*W[n,k]  (bf16x3 split, f32 acc)
//    CTA 128x128, BK=32, 8 warps (4M x 2N), warp tile 32x64.
//    96 stages = 3 passes (hi*hi, hi*lo, lo*hi) x 32 k-blocks.
//    4-stage cp.async pipeline, ONE __syncthreads per stage.
// ---------------------------------------------------------------------------
#define GSTAGES       4
#define GSTAGE_BYTES  16384
#define GEMM_SMEM     (GSTAGES * GSTAGE_BYTES)   // 64 KB

__global__ __launch_bounds__(256, 2) void gemm_mma(
    const __nv_bfloat16* __restrict__ A, const __nv_bfloat16* __restrict__ W,
    float* __restrict__ C, int epi)
{
    extern __shared__ __align__(128) char gsm[];

    const int tid = threadIdx.x;
    const int wid = tid >> 5, lane = tid & 31;
    const int wm = wid & 3;          // 0..3 -> M
    const int wn = wid >> 2;         // 0..1 -> N
    const int m0 = blockIdx.y * 128;
    const int n0 = blockIdx.x * 128;

    const uint32_t sa0 = smem_u32(gsm);

    float acc[2][8][4];
#pragma unroll
    for (int mt = 0; mt < 2; mt++)
#pragma unroll
        for (int nt = 0; nt < 8; nt++)
#pragma unroll
            for (int q = 0; q < 4; q++) acc[mt][nt][q] = 0.f;

    // loader indices: 512 A-chunks + 512 B-chunks per stage, 4 per thread
    const int lrowA = tid >> 1;                 // 0..127 (2 chunks each)
    const int lcA0 = (tid & 1) * 2;             // chunks {0,1} or {2,3}

    auto load_stage = [&](int s, int buf) {
        int p = s >> 5, kb = s & 31;
        int aoff = (p == 2) ? 1024 : 0;
        int boff = (p == 1) ? 1024 : 0;
        uint32_t ab = sa0 + buf * GSTAGE_BYTES;
        uint32_t bb = ab + 8192;
        const __nv_bfloat16* Ar = A + (size_t)(m0 + lrowA) * KD2 + aoff + kb * 32;
        const __nv_bfloat16* Br = W + (size_t)(n0 + lrowA) * KD2 + boff + kb * 32;
#pragma unroll
        for (int c = 0; c < 2; c++) {
            cp_async16(ab + swz(lrowA, lcA0 + c), Ar + (lcA0 + c) * 8);
            cp_async16(bb + swz(lrowA, lcA0 + c), Br + (lcA0 + c) * 8);
        }
    };

    const int NST = 96;
    load_stage(0, 0); CP_COMMIT();
    load_stage(1, 1); CP_COMMIT();
    load_stage(2, 2); CP_COMMIT();

    for (int s = 0; s < NST; s++) {
        CP_WAIT2();                      // stage s resident
        __syncthreads();

        // issue next loads first (into buf computed at iter s-1 -> safe)
        if (s + 3 < NST) load_stage(s + 3, (s + 3) & 3);
        CP_COMMIT();                     // unconditional: keeps group count uniform

        uint32_t ab = sa0 + (s & 3) * GSTAGE_BYTES;
        uint32_t bb = ab + 8192;
#pragma unroll
        for (int kk = 0; kk < 2; kk++) {
            uint32_t a[2][4];
#pragma unroll
            for (int mt = 0; mt < 2; mt++) {
                int row = wm * 32 + mt * 16 + (lane & 15);
                int ch = kk * 2 + (lane >> 4);
                ldm_x4(a[mt][0], a[mt][1], a[mt][2], a[mt][3], ab + swz(row, ch));
            }
            uint32_t b[8][2];
#pragma unroll
            for (int nq = 0; nq < 4; nq++) {
                int row = wn * 64 + nq * 16 + ((lane >> 4) & 1) * 8 + (lane & 7);
                int ch = kk * 2 + ((lane >> 3) & 1);
                ldm_x4(b[nq * 2][0], b[nq * 2][1], b[nq * 2 + 1][0], b[nq * 2 + 1][1],
                       bb + swz(row, ch));
            }
#pragma unroll
            for (int mt = 0; mt < 2; mt++)
#pragma unroll
                for (int nt = 0; nt < 8; nt++)
                    mma_bf16(acc[mt][nt][0], acc[mt][nt][1], acc[mt][nt][2], acc[mt][nt][3],
                             a[mt][0], a[mt][1], a[mt][2], a[mt][3],
                             b[nt][0], b[nt][1]);
        }
    }

    // epilogue: direct float2 stores
#pragma unroll
    for (int mt = 0; mt < 2; mt++) {
        int gr = m0 + wm * 32 + mt * 16 + (lane >> 2);
#pragma unroll
        for (int nt = 0; nt < 8; nt++) {
            int gc = n0 + wn * 64 + nt * 8 + (lane & 3) * 2;
            float v0 = acc[mt][nt][0], v1 = acc[mt][nt][1];
            float v2 = acc[mt][nt][2], v3 = acc[mt][nt][3];
            if (epi) {
                v0 = v0 / (1.f + expf(-v0));
                v1 = v1 / (1.f + expf(-v1));
                v2 = v2 / (1.f + expf(-v2));
                v3 = v3 / (1.f + expf(-v3));
            }
            *(float2*)&C[(size_t)gr * CC + gc]       = make_float2(v0, v1);
            *(float2*)&C[(size_t)(gr + 8) * CC + gc] = make_float2(v2, v3);
        }
    }
}

// ---------------------------------------------------------------------------
// 3a) WKV phase 1: per (b,h,chunk) contribution G = (k .* wk)^T v  (64x64)
// ---------------------------------------------------------------------------
#define P1_SMEM_BYTES ((132 + 2 * 128 * 65) * 4)

__global__ __launch_bounds__(256) void wkv_phase1(
    const float* __restrict__ Km, const float* __restrict__ V,
    float* __restrict__ G, const float* __restrict__ tdecay)
{
    extern __shared__ float sm1[];
    float* pw  = sm1;               // decay^i, 0..127
    float* k_s = sm1 + 132;         // [128][65]
    float* v_s = k_s + 128 * 65;

    const int tid = threadIdx.x;
    const int bhn = blockIdx.x;
    const int n = bhn & 31, bh = bhn >> 5;
    const int b = bh >> 4, h = bh & 15;
    const float decay = __expf(-__expf(tdecay[h]));

    for (int i = tid; i < 128; i += 256) pw[i] = powf(decay, (float)i);
    const size_t cbase = (size_t)b * TTT * CC + (size_t)h * HS + (size_t)n * TCH * CC;

    for (int e = tid; e < 128 * 16; e += 256) {
        int i = e >> 4, c4 = (e & 15) * 4;
        size_t gofs = cbase + (size_t)i * CC + c4;
        float4 kv = *(const float4*)(Km + gofs);
        float4 vv = *(const float4*)(V + gofs);
        float* kd = k_s + i * 65 + c4;
        kd[0] = kv.x; kd[1] = kv.y; kd[2] = kv.z; kd[3] = kv.w;
        float* vd = v_s + i * 65 + c4;
        vd[0] = vv.x; vd[1] = vv.y; vd[2] = vv.z; vd[3] = vv.w;
    }
    __syncthreads();

    const int tx = tid & 15, ty = tid >> 4;
    float acc[4][4];
#pragma unroll
    for (int i = 0; i < 4; i++)
#pragma unroll
        for (int j = 0; j < 4; j++) acc[i][j] = 0.f;

    for (int j = 0; j < 128; j++) {
        float wkj = pw[127 - j];
        float kw[4], vv4[4];
#pragma unroll
        for (int q = 0; q < 4; q++) {
            kw[q]  = k_s[j * 65 + ty * 4 + q] * wkj;
            vv4[q] = v_s[j * 65 + tx * 4 + q];
        }
#pragma unroll
        for (int i = 0; i < 4; i++)
#pragma unroll
            for (int c = 0; c < 4; c++)
                acc[i][c] = fmaf(kw[i], vv4[c], acc[i][c]);
    }
    float* Gd = G + (size_t)bhn * (HS * HS);
#pragma unroll
    for (int i = 0; i < 4; i++)
#pragma unroll
        for (int c = 0; c < 4; c++)
            Gd[(ty * 4 + i) * 64 + tx * 4 + c] = acc[i][c];
}

// ---------------------------------------------------------------------------
// 3b) WKV phase 2: in-place scan  buf[n] <- S_n ; S_{n+1} = ws*S_n + G_n
// ---------------------------------------------------------------------------
__global__ __launch_bounds__(256) void wkv_scan(
    float* __restrict__ G, const float* __restrict__ tdecay)
{
    const int tid = threadIdx.x;
    const int bh = blockIdx.x;
    const int h = bh & 15;
    const float decay = __expf(-__expf(tdecay[h]));
    const float ws = powf(decay, 128.f);

    float s[16];
#pragma unroll
    for (int t = 0; t < 16; t++) s[t] = 0.f;

    float* base = G + (size_t)bh * NCH * (HS * HS);
    for (int n = 0; n < NCH; n++) {
        float* p = base + (size_t)n * (HS * HS);
#pragma unroll
        for (int t = 0; t < 16; t++) {
            int idx = tid + t * 256;
            float g = p[idx];
            p[idx] = s[t];
            s[t] = ws * s[t] + g;
        }
    }
}

// ---------------------------------------------------------------------------
// 3c) WKV phase 3: per (b,h,chunk) output
// ---------------------------------------------------------------------------
#define P3_SMEM_BYTES ((132 + 3 * 128 * 65 + 128 * 129 + 64 * 65) * 4)

__global__ __launch_bounds__(256) void wkv_phase3(
    const float* __restrict__ R, const float* __restrict__ Km,
    const float* __restrict__ V, const float* __restrict__ S,
    float* __restrict__ XO,
    const float* __restrict__ tdecay, const float* __restrict__ tfaaaa)
{
    extern __shared__ float sm[];
    float* pw   = sm;
    float* r_s  = sm + 132;
    float* k_s  = r_s + 128 * 65;
    float* v_s  = k_s + 128 * 65;
    float* attS = v_s + 128 * 65;
    float* s_st = attS + 128 * 129;

    const int tid = threadIdx.x;
    const int bhn = blockIdx.x;
    const int n = bhn & 31, bh = bhn >> 5;
    const int b = bh >> 4, h = bh & 15;
    const float decay = __expf(-__expf(tdecay[h]));
    const float u = tfaaaa[h];

    for (int i = tid; i < 128; i += 256) pw[i] = powf(decay, (float)i);

    const float* Sd = S + (size_t)bhn * (HS * HS);
    for (int i = tid; i < 64 * 16; i += 256) {
        int r4 = i >> 4, c4 = (i & 15) * 4;
        float4 sv = *(const float4*)(Sd + r4 * 64 + c4);
        float* d = s_st + r4 * 65 + c4;
        d[0] = sv.x; d[1] = sv.y; d[2] = sv.z; d[3] = sv.w;
    }

    const size_t cbase = (size_t)b * TTT * CC + (size_t)h * HS + (size_t)n * TCH * CC;
    for (int e = tid; e < 128 * 16; e += 256) {
        int i = e >> 4, c4 = (e & 15) * 4;
        size_t gofs = cbase + (size_t)i * CC + c4;
        float4 rv = *(const float4*)(R + gofs);
        float4 kv = *(const float4*)(Km + gofs);
        float4 vv = *(const float4*)(V + gofs);
        float* rd = r_s + i * 65 + c4;
        rd[0] = rv.x; rd[1] = rv.y; rd[2] = rv.z; rd[3] = rv.w;
        float* kd = k_s + i * 65 + c4;
        kd[0] = kv.x; kd[1] = kv.y; kd[2] = kv.z; kd[3] = kv.w;
        float* vd = v_s + i * 65 + c4;
        vd[0] = vv.x; vd[1] = vv.y; vd[2] = vv.z; vd[3] = vv.w;
    }
    __syncthreads();

    const int tx = tid & 15, ty = tid >> 4;

    // att[i][j] = (r_i . k_j) * wmat(i,j)
    {
        float acc[8][8];
#pragma unroll
        for (int i = 0; i < 8; i++)
#pragma unroll
            for (int j = 0; j < 8; j++) acc[i][j] = 0.f;

        for (int kk = 0; kk < 64; kk++) {
            float ra[8], rb[8];
#pragma unroll
            for (int q = 0; q < 4; q++) {
                ra[q]     = r_s[(ty * 4 + q) * 65 + kk];
                ra[4 + q] = r_s[(64 + ty * 4 + q) * 65 + kk];
                rb[q]     = k_s[(tx * 4 + q) * 65 + kk];
                rb[4 + q] = k_s[(64 + tx * 4 + q) * 65 + kk];
            }
#pragma unroll
            for (int i = 0; i < 8; i++)
#pragma unroll
                for (int j = 0; j < 8; j++)
                    acc[i][j] = fmaf(ra[i], rb[j], acc[i][j]);
        }
#pragma unroll
        for (int i = 0; i < 8; i++) {
            int ri = (i < 4) ? (ty * 4 + i) : (64 + ty * 4 + (i - 4));
#pragma unroll
            for (int j = 0; j < 8; j++) {
                int cj = (j < 4) ? (tx * 4 + j) : (64 + tx * 4 + (j - 4));
                int d = ri - cj;
                float w = (d > 0) ? pw[d - 1] : ((d == 0) ? u : 0.f);
                attS[ri * 129 + cj] = acc[i][j] * w;
            }
        }
    }
    __syncthreads();

    // out[i][c] = sum_j att[i][j]*v[j][c] + pw[i]*sum_k r[i][k]*s[k][c]
    {
        float acc2[8][4], acc3[8][4];
#pragma unroll
        for (int i = 0; i < 8; i++)
#pragma unroll
            for (int j = 0; j < 4; j++) { acc2[i][j] = 0.f; acc3[i][j] = 0.f; }

        for (int j = 0; j < 128; j++) {
            float a[8], vv4[4];
#pragma unroll
            for (int q = 0; q < 4; q++) {
                a[q]     = attS[(ty * 4 + q) * 129 + j];
                a[4 + q] = attS[(64 + ty * 4 + q) * 129 + j];
                vv4[q]   = v_s[j * 65 + tx * 4 + q];
            }
#pragma unroll
            for (int i = 0; i < 8; i++)
#pragma unroll
                for (int c = 0; c < 4; c++)
                    acc2[i][c] = fmaf(a[i], vv4[c], acc2[i][c]);
        }
        for (int kk = 0; kk < 64; kk++) {
            float a[8], sv[4];
#pragma unroll
            for (int q = 0; q < 4; q++) {
                a[q]     = r_s[(ty * 4 + q) * 65 + kk];
                a[4 + q] = r_s[(64 + ty * 4 + q) * 65 + kk];
                sv[q]    = s_st[kk * 65 + tx * 4 + q];
            }
#pragma unroll
            for (int i = 0; i < 8; i++)
#pragma unroll
                for (int c = 0; c < 4; c++)
                    acc3[i][c] = fmaf(a[i], sv[c], acc3[i][c]);
        }
#pragma unroll
        for (int i = 0; i < 8; i++) {
            int ri = (i < 4) ? (ty * 4 + i) : (64 + ty * 4 + (i - 4));
            float wbv = pw[ri];
#pragma unroll
            for (int c = 0; c < 4; c++)
                XO[cbase + (size_t)ri * CC + tx * 4 + c] =
                    acc2[i][c] + wbv * acc3[i][c];
        }
    }
}

// ---------------------------------------------------------------------------
// 4) GroupNorm + gate -> bf16 hi/lo output for final GEMM
// ---------------------------------------------------------------------------
__global__ __launch_bounds__(256) void gn_gate_kernel(
    const float* __restrict__ xo, const float* __restrict__ gg,
    const float* __restrict__ lnw, const float* __restrict__ lnb,
    __nv_bfloat16* __restrict__ yg)
{
    int warp = threadIdx.x >> 5, lane = threadIdx.x & 31;
    int gw = blockIdx.x * 8 + warp;   // over MM*HH
    int h = gw % HH;
    int row = gw / HH;
    size_t base = (size_t)row * CC + h * HS;

    float a = xo[base + lane] * 0.125f;
    float b = xo[base + 32 + lane] * 0.125f;
    float s = a + b, ss = a * a + b * b;
#pragma unroll
    for (int o = 16; o > 0; o >>= 1) {
        s  += __shfl_xor_sync(0xffffffffu, s,  o);
        ss += __shfl_xor_sync(0xffffffffu, ss, o);
    }
    float mean = s * (1.f / 64.f);
    float var  = ss * (1.f / 64.f) - mean * mean;
    float inv  = rsqrtf(var + 1e-5f);

    int c0 = h * HS + lane, c1 = c0 + 32;
    float y0 = ((a - mean) * inv * lnw[c0] + lnb[c0]) * gg[base + lane];
    float y1 = ((b - mean) * inv * lnw[c1] + lnb[c1]) * gg[base + 32 + lane];

    size_t b2 = (size_t)row * KD2;
    __nv_bfloat16 h0, l0, h1, l1;
    split_bf16(y0, h0, l0);
    split_bf16(y1, h1, l1);
    yg[b2 + c0]         = h0;
    yg[b2 + c1]         = h1;
    yg[b2 + 1024 + c0]  = l0;
    yg[b2 + 1024 + c1]  = l1;
}

// ---------------------------------------------------------------------------
// Launch
// ---------------------------------------------------------------------------
extern "C" void kernel_launch(void* const* d_in, const int* in_sizes, int n_in,
                              void* d_out, int out_size)
{
    const float* x      = (const float*)d_in[0];
    const float* tmk    = (const float*)d_in[1];
    const float* tmv    = (const float*)d_in[2];
    const float* tmr    = (const float*)d_in[3];
    const float* tmg    = (const float*)d_in[4];
    const float* tdecay = (const float*)d_in[5];
    const float* tfaaaa = (const float*)d_in[6];
    const float* Wr     = (const float*)d_in[7];
    const float* Wk     = (const float*)d_in[8];
    const float* Wv     = (const float*)d_in[9];
    const float* Wg     = (const float*)d_in[10];
    const float* Wo     = (const float*)d_in[11];
    const float* lnw    = (const float*)d_in[12];
    const float* lnb    = (const float*)d_in[13];
    float* out = (float*)d_out;

    __nv_bfloat16 *xr, *xk, *xv, *xg, *ygb, *wr, *wk, *wv, *wg, *wo;
    float *r, *k, *v, *g, *xo, *st;
    cudaGetSymbolAddress((void**)&xr,  g_xr);
    cudaGetSymbolAddress((void**)&xk,  g_xk);
    cudaGetSymbolAddress((void**)&xv,  g_xv);
    cudaGetSymbolAddress((void**)&xg,  g_xg);
    cudaGetSymbolAddress((void**)&ygb, g_ygb);
    cudaGetSymbolAddress((void**)&wr,  g_Wr);
    cudaGetSymbolAddress((void**)&wk,  g_Wk);
    cudaGetSymbolAddress((void**)&wv,  g_Wv);
    cudaGetSymbolAddress((void**)&wg,  g_Wg);
    cudaGetSymbolAddress((void**)&wo,  g_Wo);
    cudaGetSymbolAddress((void**)&r,   g_r);
    cudaGetSymbolAddress((void**)&k,   g_k);
    cudaGetSymbolAddress((void**)&v,   g_v);
    cudaGetSymbolAddress((void**)&g,   g_g);
    cudaGetSymbolAddress((void**)&xo,  g_xo);
    cudaGetSymbolAddress((void**)&st,  g_state);

    cudaFuncSetAttribute(gemm_mma,
                         cudaFuncAttributeMaxDynamicSharedMemorySize, GEMM_SMEM);
    cudaFuncSetAttribute(wkv_phase1,
                         cudaFuncAttributeMaxDynamicSharedMemorySize, P1_SMEM_BYTES);
    cudaFuncSetAttribute(wkv_phase3,
                         cudaFuncAttributeMaxDynamicSharedMemorySize, P3_SMEM_BYTES);

    // 0) weight hi/lo conversion (single launch, 5 weights)
    {
        dim3 cgrid((CC * CC + 255) / 256, 5);
        convw_kernel<<<cgrid, 256>>>(Wr, Wk, Wv, Wg, Wo, wr, wk, wv, wg, wo);
    }

    // 1) mix -> bf16 hi/lo
    {
        int total4 = MM * CC / 4;
        mix_kernel<<<(total4 + 255) / 256, 256>>>(x, tmk, tmv, tmr, tmg,
                                                  xr, xk, xv, xg);
    }

    // 2) projections on tensor cores (mma.sync, 4-stage pipeline)
    dim3 ggrid(CC / 128, MM / 128);   // (8, 128)
    gemm_mma<<<ggrid, 256, GEMM_SMEM>>>(xr, wr, r, 0);
    gemm_mma<<<ggrid, 256, GEMM_SMEM>>>(xk, wk, k, 0);
    gemm_mma<<<ggrid, 256, GEMM_SMEM>>>(xv, wv, v, 0);
    gemm_mma<<<ggrid, 256, GEMM_SMEM>>>(xg, wg, g, 1);   // silu

    // 3) WKV: parallel contributions -> scan -> parallel outputs
    wkv_phase1<<<BB * HH * NCH, 256, P1_SMEM_BYTES>>>(k, v, st, tdecay);
    wkv_scan<<<BB * HH, 256>>>(st, tdecay);
    wkv_phase3<<<BB * HH * NCH, 256, P3_SMEM_BYTES>>>(r, k, v, st, xo,
                                                      tdecay, tfaaaa);

    // 4) GroupNorm + gate -> bf16 hi/lo
    gn_gate_kernel<<<MM * HH / 8, 256>>>(xo, g, lnw, lnb, ygb);

    // 5) output projection (writes d_out)
    gemm_mma<<<ggrid, 256, GEMM_SMEM>>>(ygb, wo, out, 0);
}